// round 7
// baseline (speedup 1.0000x reference)
#include <cuda_runtime.h>
#include <cuda_bf16.h>
#include <cstdint>

// ---------------------------------------------------------------------------
// NodeUnpool via int8 IMMA (m16n8k32.s8), 2-limb fixed-point, global scales:
//   out = h_full;  out[idx] = h_full[idx]@W1^T + b1 + h_sub@W2^T + b2
// C[M,256] = [h_full[idx] | h_sub] @ [W1 | W2]^T   (K = 512 concat)
//
// a = sA*(a_hi*128 + a_lo), b = sB*(b_hi*128 + b_lo); result =
//   sA*sB*(16384*acc_hh + 128*acc_mid), acc_mid = A_hi*B_lo + A_lo*B_hi.
// (ll term dropped: ~2e-4 relative). A range +-7 sigma, B +-6 sigma.
// Masked copy of non-pooled rows overlaps GEMM on a second stream.
// ---------------------------------------------------------------------------

#define DIM      256
#define BM       128
#define BN       128
#define KC       64
#define THREADS  512

#define QMAXF    16256.0f
#define RANGE_A  7.0f
#define RANGE_B  0.375f
#define INV_SA   (QMAXF / RANGE_A)
#define INV_SB   (QMAXF / RANGE_B)
#define SC_HH    ((RANGE_A / QMAXF) * (RANGE_B / QMAXF) * 16384.0f)
#define SC_MID   ((RANGE_A / QMAXF) * (RANGE_B / QMAXF) * 128.0f)

// smem layout (bytes): stride 80 per 64-byte row (conflict-free, 16B aligned)
#define ROWB      80
#define LIMB_SZ   (128 * ROWB)        // 10240
#define STAGE_SZ  (2 * LIMB_SZ)       // hi + lo = 20480
#define SM_ROWIDX 0                   // int[128]
#define SM_BIAS   512                 // float[128]
#define SM_A      1024                // 2 stages x 20480
#define SM_B      (SM_A + 2 * STAGE_SZ)     // 41984
#define SM_TOTAL  (SM_B + 2 * STAGE_SZ)     // 82944

#define MASK_CAP  (2u << 20)

__device__ int g_idx_is64;
__device__ __align__(16) char g_Bhi[256 * 512];   // [n][kcat] int8 hi limb
__device__ __align__(16) char g_Blo[256 * 512];   // [n][kcat] int8 lo limb
__device__ __align__(16) unsigned char g_mask[MASK_CAP];  // 1 = pooled row

// ---------------- helpers ----------------
__device__ __forceinline__ uint32_t smem_u32(const void* p) {
    uint32_t a;
    asm("{ .reg .u64 t; cvta.to.shared.u64 t, %1; cvt.u32.u64 %0, t; }"
        : "=r"(a) : "l"(p));
    return a;
}
__device__ __forceinline__ void cp_async16(uint32_t dst, const void* src) {
    asm volatile("cp.async.cg.shared.global [%0], [%1], 16;"
                 :: "r"(dst), "l"(src) : "memory");
}
__device__ __forceinline__ void cp_commit() {
    asm volatile("cp.async.commit_group;" ::: "memory");
}
__device__ __forceinline__ void cp_wait0() {
    asm volatile("cp.async.wait_group 0;" ::: "memory");
}
__device__ __forceinline__ uint32_t lds32(uint32_t addr) {
    uint32_t v;
    asm volatile("ld.shared.b32 %0, [%1];" : "=r"(v) : "r"(addr));
    return v;
}
__device__ __forceinline__ void imma(int* d, const uint32_t* a,
                                     uint32_t b0, uint32_t b1) {
    asm volatile(
        "mma.sync.aligned.m16n8k32.row.col.s32.s8.s8.s32 "
        "{%0,%1,%2,%3}, {%4,%5,%6,%7}, {%8,%9}, {%0,%1,%2,%3};"
        : "+r"(d[0]), "+r"(d[1]), "+r"(d[2]), "+r"(d[3])
        : "r"(a[0]), "r"(a[1]), "r"(a[2]), "r"(a[3]), "r"(b0), "r"(b1));
}
// quantize 4 floats -> packed hi byte u32 + lo byte u32
__device__ __forceinline__ void quant4(float4 v, float invS,
                                       uint32_t& ph, uint32_t& pl) {
    int q0 = __float2int_rn(v.x * invS);
    int q1 = __float2int_rn(v.y * invS);
    int q2 = __float2int_rn(v.z * invS);
    int q3 = __float2int_rn(v.w * invS);
    q0 = max(-16256, min(16256, q0));
    q1 = max(-16256, min(16256, q1));
    q2 = max(-16256, min(16256, q2));
    q3 = max(-16256, min(16256, q3));
    int h0 = (q0 + 64) >> 7, h1 = (q1 + 64) >> 7;
    int h2 = (q2 + 64) >> 7, h3 = (q3 + 64) >> 7;
    int l0 = q0 - (h0 << 7), l1 = q1 - (h1 << 7);
    int l2 = q2 - (h2 << 7), l3 = q3 - (h3 << 7);
    ph = __byte_perm(__byte_perm(h0, h1, 0x0040),
                     __byte_perm(h2, h3, 0x0040), 0x5410);
    pl = __byte_perm(__byte_perm(l0, l1, 0x0040),
                     __byte_perm(l2, l3, 0x0040), 0x5410);
}

// ---------------- idx dtype detection ----------------
__device__ __forceinline__ long long load_idx(const void* idx, int r, int is64) {
    if (is64) return reinterpret_cast<const long long*>(idx)[r];
    return (long long)reinterpret_cast<const int*>(idx)[r];
}
__global__ void detect_idx_kernel(const void* idx, int Mrows, long long Nfull) {
    const long long* p64 = reinterpret_cast<const long long*>(idx);
    int n = Mrows / 2;
    if (n > 8) n = 8;
    bool ok64 = (n > 0);
    for (int i = 0; i < n; ++i) {
        long long v = p64[i];
        if (v < 0 || v >= Nfull) { ok64 = false; break; }
    }
    g_idx_is64 = ok64 ? 1 : 0;
}

// ---------------- mask clear / set ----------------
__global__ void clear_mask(int nWords) {
    int t = blockIdx.x * blockDim.x + threadIdx.x;
    uint4* p = reinterpret_cast<uint4*>(g_mask);
    if (t < nWords) p[t] = make_uint4(0, 0, 0, 0);
}
__global__ void set_mask(const void* __restrict__ idx, int Mrows) {
    int t = blockIdx.x * blockDim.x + threadIdx.x;
    if (t < Mrows) {
        long long g = load_idx(idx, t, g_idx_is64);
        g_mask[g] = 1;
    }
}

// ---------------- W -> int8 hi/lo limbs, [n][kcat] ----------------
__global__ void convert_W(const float* __restrict__ W1, const float* __restrict__ W2) {
    int t = blockIdx.x * blockDim.x + threadIdx.x;   // 256*512
    if (t >= 256 * 512) return;
    int n    = t >> 9;
    int kcat = t & 511;
    float x = (kcat < DIM) ? W1[n * DIM + kcat] : W2[n * DIM + (kcat - DIM)];
    int q = __float2int_rn(x * INV_SB);
    q = max(-16256, min(16256, q));
    int hi = (q + 64) >> 7;
    int lo = q - (hi << 7);
    g_Bhi[t] = (char)hi;
    g_Blo[t] = (char)lo;
}

// ---------------- masked row copy (skips pooled rows) ----------------
__global__ __launch_bounds__(256)
void masked_copy(const float* __restrict__ h_full,
                 float* __restrict__ out, int Nfull)
{
    const float4* in4  = reinterpret_cast<const float4*>(h_full);
    float4*       out4 = reinterpret_cast<float4*>(out);
    const size_t total = (size_t)Nfull * (DIM / 4);
    const size_t step  = (size_t)gridDim.x * blockDim.x;
    size_t g = (size_t)blockIdx.x * blockDim.x + threadIdx.x;
#pragma unroll 4
    for (; g < total; g += step) {
        int r = (int)(g >> 6);
        if (!g_mask[r]) out4[g] = in4[g];
    }
}

// ---------------- main GEMM (int8 IMMA) ----------------
__global__ __launch_bounds__(THREADS, 1)
void merge_gemm_imma(const float* __restrict__ h_full,
                     const float* __restrict__ h_sub,
                     const float* __restrict__ b1,
                     const float* __restrict__ b2,
                     const void*  __restrict__ idx,
                     float* __restrict__ out,
                     int Mrows)
{
    extern __shared__ __align__(16) char smem[];
    const uint32_t sbase = smem_u32(smem);

    const int tid   = threadIdx.x;
    const int wid   = tid >> 5;
    const int lid   = tid & 31;
    const int tileM = blockIdx.x * BM;
    const int nBase = blockIdx.y * BN;
    const int warpM = (wid & 7) * 16;      // 8 warps stacked in M
    const int warpN = (wid >> 3) * 64;     // 2 groups in N

    int*   rowidx = (int*)(smem + SM_ROWIDX);
    float* biasS  = (float*)(smem + SM_BIAS);

    const int is64 = g_idx_is64;
    if (tid < BM) {
        int m = tileM + tid;
        rowidx[tid] = (m < Mrows) ? (int)load_idx(idx, m, is64) : 0;
        biasS[tid]  = b1[nBase + tid] + b2[nBase + tid];
    }
    __syncthreads();

    // ---- B stage fill via cp.async (chunk c -> stage st), hi+lo limbs
    auto issueB = [&](int c, int st) {
        uint32_t dbase = sbase + SM_B + st * STAGE_SZ;
#pragma unroll
        for (int j = 0; j < 2; ++j) {
            int id   = tid + j * THREADS;    // 0..1023
            int row  = id >> 3;              // 0..127
            int sub  = id & 7;
            int limb = sub >> 2;             // 0 = hi, 1 = lo
            int seg  = sub & 3;              // 16B segment within 64B row
            uint32_t dst = dbase + limb * LIMB_SZ + row * ROWB + seg * 16;
            const char* src = (limb ? g_Blo : g_Bhi)
                            + ((size_t)(nBase + row) << 9) + c * KC + seg * 16;
            cp_async16(dst, src);
        }
    };

    // ---- A chunk gather into regs: thread t -> row t>>2, 16 floats
    const int aRow = tid >> 2;
    const int aQ   = tid & 3;
    auto loadA = [&](float4* dst, int c) {
        const float* src;
        if (c < 4) {
            src = h_full + (size_t)rowidx[aRow] * DIM + c * KC;
        } else {
            int m = tileM + aRow;
            if (m >= Mrows) m = Mrows - 1;
            src = h_sub + (size_t)m * DIM + (c - 4) * KC;
        }
#pragma unroll
        for (int j = 0; j < 4; ++j)
            dst[j] = *(const float4*)(src + aQ * 16 + j * 4);
    };

    // ---- quantize A regs -> hi/lo int8 smem (stage st)
    auto storeA = [&](const float4* v, int st) {
        uint32_t ph[4], pl[4];
#pragma unroll
        for (int j = 0; j < 4; ++j) quant4(v[j], INV_SA, ph[j], pl[j]);
        uint32_t off = sbase + SM_A + st * STAGE_SZ + aRow * ROWB + aQ * 16;
        *(uint4*)(smem + (off - sbase)) = make_uint4(ph[0], ph[1], ph[2], ph[3]);
        *(uint4*)(smem + (off - sbase) + LIMB_SZ) =
            make_uint4(pl[0], pl[1], pl[2], pl[3]);
    };

    int hh[8][4], mid[8][4];
#pragma unroll
    for (int nt = 0; nt < 8; ++nt)
#pragma unroll
        for (int q = 0; q < 4; ++q) { hh[nt][q] = 0; mid[nt][q] = 0; }

    // ---- compute one KC=64 chunk from stage st
    auto compute = [&](int st) {
        const uint32_t aB = sbase + SM_A + st * STAGE_SZ;
        const uint32_t bB = sbase + SM_B + st * STAGE_SZ;
        const uint32_t rA = (uint32_t)(warpM + (lid >> 2)) * ROWB + (lid & 3) * 4;
#pragma unroll
        for (int kk = 0; kk < 2; ++kk) {
            const uint32_t kb = kk * 32;
            uint32_t ahi[4], alo[4];
            ahi[0] = lds32(aB + rA + kb);
            ahi[1] = lds32(aB + rA + 8 * ROWB + kb);
            ahi[2] = lds32(aB + rA + kb + 16);
            ahi[3] = lds32(aB + rA + 8 * ROWB + kb + 16);
            alo[0] = lds32(aB + LIMB_SZ + rA + kb);
            alo[1] = lds32(aB + LIMB_SZ + rA + 8 * ROWB + kb);
            alo[2] = lds32(aB + LIMB_SZ + rA + kb + 16);
            alo[3] = lds32(aB + LIMB_SZ + rA + 8 * ROWB + kb + 16);
#pragma unroll
            for (int nt = 0; nt < 8; ++nt) {
                uint32_t rB = (uint32_t)(warpN + nt * 8 + (lid >> 2)) * ROWB
                            + (lid & 3) * 4 + kb;
                uint32_t bh0 = lds32(bB + rB);
                uint32_t bh1 = lds32(bB + rB + 16);
                uint32_t bl0 = lds32(bB + LIMB_SZ + rB);
                uint32_t bl1 = lds32(bB + LIMB_SZ + rB + 16);
                imma(hh[nt],  ahi, bh0, bh1);
                imma(mid[nt], ahi, bl0, bl1);
                imma(mid[nt], alo, bh0, bh1);
            }
        }
    };

    // ---- prologue: chunk 0 into stage 0
    float4 aPre[4];
    issueB(0, 0);
    cp_commit();
    loadA(aPre, 0);
    storeA(aPre, 0);
    cp_wait0();
    __syncthreads();

    // ---- main loop: one sync per chunk (A and B both double-buffered)
#pragma unroll 1
    for (int c = 0; c < 8; ++c) {
        const int st = c & 1;
        if (c < 7) {
            issueB(c + 1, st ^ 1);
            cp_commit();
            loadA(aPre, c + 1);
        }
        compute(st);
        if (c < 7) {
            storeA(aPre, st ^ 1);
            cp_wait0();
        }
        __syncthreads();
    }

    // ---- epilogue: combine limbs, add bias, scatter
    {
        const float shh = SC_HH, smid = SC_MID;
        const int nc = (lid & 3) * 2;
#pragma unroll
        for (int half = 0; half < 2; ++half) {
            int row = warpM + (lid >> 2) + half * 8;
            int mg  = tileM + row;
            if (mg < Mrows) {
                float* orow = out + (size_t)rowidx[row] * DIM + nBase + warpN;
#pragma unroll
                for (int nt = 0; nt < 8; ++nt) {
                    int cb = warpN + nt * 8 + nc;
                    float2 v;
                    v.x = fmaf(shh, (float)hh[nt][half * 2 + 0],
                          fmaf(smid, (float)mid[nt][half * 2 + 0], biasS[cb]));
                    v.y = fmaf(shh, (float)hh[nt][half * 2 + 1],
                          fmaf(smid, (float)mid[nt][half * 2 + 1], biasS[cb + 1]));
                    *(float2*)(orow + nt * 8 + nc) = v;
                }
            }
        }
    }
}

// ---------------- launch ----------------
extern "C" void kernel_launch(void* const* d_in, const int* in_sizes, int n_in,
                              void* d_out, int out_size) {
    const float* h_full = (const float*)d_in[0];
    const float* h_sub  = (const float*)d_in[1];
    const float* W1     = (const float*)d_in[2];
    const float* b1     = (const float*)d_in[3];
    const float* W2     = (const float*)d_in[4];
    const float* b2     = (const float*)d_in[5];
    const void*  idx    = d_in[6];
    float*       out    = (float*)d_out;

    const int dim   = in_sizes[3];
    const int Mrows = in_sizes[1] / dim;
    const int Nfull = in_sizes[0] / dim;

    static cudaStream_t sCopy = nullptr;
    static cudaEvent_t  evFork = nullptr, evJoin = nullptr;
    if (!sCopy) {
        cudaStreamCreateWithFlags(&sCopy, cudaStreamNonBlocking);
        cudaEventCreateWithFlags(&evFork, cudaEventDisableTiming);
        cudaEventCreateWithFlags(&evJoin, cudaEventDisableTiming);
    }

    cudaFuncSetAttribute(merge_gemm_imma,
                         cudaFuncAttributeMaxDynamicSharedMemorySize, SM_TOTAL);

    // prep (stream 0): dtype detect, W quantize, mask build
    detect_idx_kernel<<<1, 1>>>(idx, Mrows, (long long)Nfull);
    convert_W<<<(256 * 512 + 255) / 256, 256>>>(W1, W2);
    const int maskWords = (Nfull + 15) / 16;
    clear_mask<<<(maskWords + 255) / 256, 256>>>(maskWords);
    set_mask<<<(Mrows + 255) / 256, 256>>>(idx, Mrows);

    // fork: masked copy on sCopy, GEMM on stream 0 (disjoint writes)
    cudaEventRecord(evFork, 0);
    cudaStreamWaitEvent(sCopy, evFork, 0);

    masked_copy<<<2048, 256, 0, sCopy>>>(h_full, out, Nfull);

    const int tiles = (Mrows + BM - 1) / BM;
    dim3 grid((unsigned)tiles, (unsigned)(dim / BN));
    merge_gemm_imma<<<grid, THREADS, SM_TOTAL>>>(h_full, h_sub, b1, b2, idx,
                                                 out, Mrows);

    // join
    cudaEventRecord(evJoin, sCopy);
    cudaStreamWaitEvent(0, evJoin, 0);
}

// round 8
// speedup vs baseline: 3.0942x; 3.0942x over previous
#include <cuda_runtime.h>
#include <cuda_fp16.h>
#include <cstdint>

// ---------------------------------------------------------------------------
// NodeUnpool via fp16 HMMA (m16n8k16.f16, fp32 accumulate), single product:
//   out = h_full;  out[idx] = h_full[idx]@W1^T + b1 + h_sub@W2^T + b2
// C[M,256] = [h_full[idx] | h_sub] @ [W1 | W2]^T   (K = 512 concat)
//
// fp16 quantization noise -> dot rel err ~4e-4 (validated model), well under
// the 1e-3 gate. 3x fewer HMMA than the bf16 split version.
// Masked copy of non-pooled rows overlaps the GEMM on a second stream.
// ---------------------------------------------------------------------------

#define DIM      256
#define BM       128
#define BN       128
#define KC       64
#define THREADS  256
#define ROWB     144            // 64 halves = 128B + 16B pad (conflict-free)

// smem layout (bytes)
#define SM_ROWIDX 0             // int[128]
#define SM_BIAS   512           // float[128]
#define STAGE_SZ  (128 * ROWB)  // 18432
#define SM_A      1024          // 2 stages
#define SM_B      (SM_A + 2 * STAGE_SZ)     // 37888
#define SM_TOTAL  (SM_B + 2 * STAGE_SZ)     // 74752

#define MASK_CAP  (2u << 20)

__device__ int g_idx_is64;
__device__ __align__(16) __half g_Bw[256 * 512];          // [n][kcat] fp16
__device__ __align__(16) unsigned char g_mask[MASK_CAP];  // 1 = pooled row

// ---------------- helpers ----------------
__device__ __forceinline__ uint32_t smem_u32(const void* p) {
    uint32_t a;
    asm("{ .reg .u64 t; cvta.to.shared.u64 t, %1; cvt.u32.u64 %0, t; }"
        : "=r"(a) : "l"(p));
    return a;
}
__device__ __forceinline__ void cp_async16(uint32_t dst, const void* src) {
    asm volatile("cp.async.cg.shared.global [%0], [%1], 16;"
                 :: "r"(dst), "l"(src) : "memory");
}
__device__ __forceinline__ void cp_commit() {
    asm volatile("cp.async.commit_group;" ::: "memory");
}
__device__ __forceinline__ void cp_wait0() {
    asm volatile("cp.async.wait_group 0;" ::: "memory");
}
__device__ __forceinline__ void ldsm4(uint32_t* r, uint32_t addr) {
    asm volatile("ldmatrix.sync.aligned.m8n8.x4.shared.b16 {%0,%1,%2,%3}, [%4];"
                 : "=r"(r[0]), "=r"(r[1]), "=r"(r[2]), "=r"(r[3]) : "r"(addr));
}
__device__ __forceinline__ uint32_t lds32(uint32_t addr) {
    uint32_t v;
    asm volatile("ld.shared.b32 %0, [%1];" : "=r"(v) : "r"(addr));
    return v;
}
__device__ __forceinline__ void hmma(float* d, const uint32_t* a,
                                     uint32_t b0, uint32_t b1) {
    asm volatile(
        "mma.sync.aligned.m16n8k16.row.col.f32.f16.f16.f32 "
        "{%0,%1,%2,%3}, {%4,%5,%6,%7}, {%8,%9}, {%0,%1,%2,%3};"
        : "+f"(d[0]), "+f"(d[1]), "+f"(d[2]), "+f"(d[3])
        : "r"(a[0]), "r"(a[1]), "r"(a[2]), "r"(a[3]), "r"(b0), "r"(b1));
}

// ---------------- idx dtype detection ----------------
__device__ __forceinline__ long long load_idx(const void* idx, int r, int is64) {
    if (is64) return reinterpret_cast<const long long*>(idx)[r];
    return (long long)reinterpret_cast<const int*>(idx)[r];
}
__global__ void detect_idx_kernel(const void* idx, int Mrows, long long Nfull) {
    const long long* p64 = reinterpret_cast<const long long*>(idx);
    int n = Mrows / 2;
    if (n > 8) n = 8;
    bool ok64 = (n > 0);
    for (int i = 0; i < n; ++i) {
        long long v = p64[i];
        if (v < 0 || v >= Nfull) { ok64 = false; break; }
    }
    g_idx_is64 = ok64 ? 1 : 0;
}

// ---------------- mask clear / set ----------------
__global__ void clear_mask(int nWords) {
    int t = blockIdx.x * blockDim.x + threadIdx.x;
    uint4* p = reinterpret_cast<uint4*>(g_mask);
    if (t < nWords) p[t] = make_uint4(0, 0, 0, 0);
}
__global__ void set_mask(const void* __restrict__ idx, int Mrows) {
    int t = blockIdx.x * blockDim.x + threadIdx.x;
    if (t < Mrows) {
        long long g = load_idx(idx, t, g_idx_is64);
        g_mask[g] = 1;
    }
}

// ---------------- W -> fp16, [n][kcat] ----------------
__global__ void convert_W(const float* __restrict__ W1, const float* __restrict__ W2) {
    int t = blockIdx.x * blockDim.x + threadIdx.x;   // 256*512
    if (t >= 256 * 512) return;
    int n    = t >> 9;
    int kcat = t & 511;
    float x = (kcat < DIM) ? W1[n * DIM + kcat] : W2[n * DIM + (kcat - DIM)];
    g_Bw[t] = __float2half_rn(x);
}

// ---------------- masked row copy (skips pooled rows) ----------------
__global__ __launch_bounds__(256)
void masked_copy(const float* __restrict__ h_full,
                 float* __restrict__ out, int Nfull)
{
    const float4* in4  = reinterpret_cast<const float4*>(h_full);
    float4*       out4 = reinterpret_cast<float4*>(out);
    const size_t total = (size_t)Nfull * (DIM / 4);
    const size_t step  = (size_t)gridDim.x * blockDim.x;
    size_t g = (size_t)blockIdx.x * blockDim.x + threadIdx.x;
#pragma unroll 4
    for (; g < total; g += step) {
        int r = (int)(g >> 6);
        if (!g_mask[r]) out4[g] = in4[g];
    }
}

// ---------------- main GEMM (fp16 HMMA, single product) ----------------
__global__ __launch_bounds__(THREADS, 2)
void merge_gemm_fp16(const float* __restrict__ h_full,
                     const float* __restrict__ h_sub,
                     const float* __restrict__ b1,
                     const float* __restrict__ b2,
                     const void*  __restrict__ idx,
                     float* __restrict__ out,
                     int Mrows)
{
    extern __shared__ __align__(16) char smem[];
    const uint32_t sbase = smem_u32(smem);

    const int tid   = threadIdx.x;
    const int wid   = tid >> 5;
    const int lid   = tid & 31;
    const int tileM = blockIdx.x * BM;
    const int nBase = blockIdx.y * BN;
    const int warpM = (wid & 3) * 32;
    const int warpN = (wid >> 2) * 64;

    int*   rowidx = (int*)(smem + SM_ROWIDX);
    float* biasS  = (float*)(smem + SM_BIAS);

    const int is64 = g_idx_is64;
    if (tid < BM) {
        int m = tileM + tid;
        rowidx[tid] = (m < Mrows) ? (int)load_idx(idx, m, is64) : 0;
        biasS[tid]  = b1[nBase + tid] + b2[nBase + tid];
    }
    __syncthreads();

    // ---- B stage fill via cp.async: 128 rows x 128B -> 1024 x 16B segs
    auto issueB = [&](int c, int st) {
        uint32_t dbase = sbase + SM_B + st * STAGE_SZ;
#pragma unroll
        for (int j = 0; j < 4; ++j) {
            int id  = tid + j * THREADS;     // 0..1023
            int row = id >> 3;               // 0..127
            int seg = id & 7;                // 16B segment
            uint32_t dst = dbase + row * ROWB + seg * 16;
            const char* src = (const char*)g_Bw
                            + (((size_t)(nBase + row) << 9) + c * KC + seg * 8) * 2;
            cp_async16(dst, src);
        }
    };

    // ---- A chunk gather into regs: 2048 float4, 8 per thread
    auto loadA = [&](float4* dst, int c) {
        const bool fromFull = (c < 4);
        const int  kb = (c & 3) * KC;
#pragma unroll
        for (int j = 0; j < 8; ++j) {
            int id = tid + j * THREADS;
            int r  = id >> 4;                // 0..127
            int c4 = (id & 15) << 2;         // 0..60
            const float* src;
            if (fromFull) {
                src = h_full + (size_t)rowidx[r] * DIM;
            } else {
                int m = tileM + r;
                if (m >= Mrows) m = Mrows - 1;
                src = h_sub + (size_t)m * DIM;
            }
            dst[j] = *(const float4*)(src + kb + c4);
        }
    };

    // ---- A regs -> fp16 smem (stage st)
    auto storeA = [&](const float4* v, int st) {
        uint32_t abase = (uint32_t)(SM_A + st * STAGE_SZ);
#pragma unroll
        for (int j = 0; j < 8; ++j) {
            int id = tid + j * THREADS;
            int r  = id >> 4;
            int c4 = (id & 15) << 2;
            float4 q = v[j];
            __half2 p01 = __floats2half2_rn(q.x, q.y);
            __half2 p23 = __floats2half2_rn(q.z, q.w);
            *(uint2*)(smem + abase + r * ROWB + c4 * 2) =
                make_uint2(*(uint32_t*)&p01, *(uint32_t*)&p23);
        }
    };

    float acc[2][8][4];
#pragma unroll
    for (int mt = 0; mt < 2; ++mt)
#pragma unroll
        for (int nt = 0; nt < 8; ++nt)
#pragma unroll
            for (int q = 0; q < 4; ++q) acc[mt][nt][q] = 0.f;

    // ---- compute one KC=64 chunk from stage st
    auto compute = [&](int st) {
        const uint32_t aB = sbase + SM_A + st * STAGE_SZ;
        const uint32_t bB = sbase + SM_B + st * STAGE_SZ;
#pragma unroll
        for (int kk = 0; kk < 4; ++kk) {
            uint32_t a[2][4];
#pragma unroll
            for (int mt = 0; mt < 2; ++mt) {
                uint32_t ra = (uint32_t)(warpM + mt * 16 + (lid & 15)) * ROWB
                            + (kk * 16 + (lid >> 4) * 8) * 2;
                ldsm4(a[mt], aB + ra);
            }
#pragma unroll
            for (int nt = 0; nt < 8; ++nt) {
                uint32_t rb = bB + (uint32_t)(warpN + nt * 8 + (lid >> 2)) * ROWB
                            + (kk * 16 + (lid & 3) * 2) * 2;
                uint32_t b0 = lds32(rb), b1v = lds32(rb + 16);
#pragma unroll
                for (int mt = 0; mt < 2; ++mt)
                    hmma(acc[mt][nt], a[mt], b0, b1v);
            }
        }
    };

    // ---- prologue: chunk 0 into stage 0
    float4 aPre[8];
    issueB(0, 0);
    cp_commit();
    loadA(aPre, 0);
    storeA(aPre, 0);
    cp_wait0();
    __syncthreads();

    // ---- main loop: one sync per chunk (A and B double-buffered)
#pragma unroll 1
    for (int c = 0; c < 8; ++c) {
        const int st = c & 1;
        if (c < 7) {
            issueB(c + 1, st ^ 1);
            cp_commit();
            loadA(aPre, c + 1);
        }
        compute(st);
        if (c < 7) {
            storeA(aPre, st ^ 1);
            cp_wait0();
        }
        __syncthreads();
    }

    // ---- epilogue: bias add + scatter
    {
        const int r0 = lid >> 2;
        const int nc = (lid & 3) * 2;
#pragma unroll
        for (int mt = 0; mt < 2; ++mt) {
#pragma unroll
            for (int half = 0; half < 2; ++half) {
                int row = warpM + mt * 16 + r0 + half * 8;
                int mg  = tileM + row;
                if (mg < Mrows) {
                    float* orow = out + (size_t)rowidx[row] * DIM + nBase + warpN;
#pragma unroll
                    for (int nt = 0; nt < 8; ++nt) {
                        float2 bv = *(const float2*)&biasS[warpN + nt * 8 + nc];
                        float2 v;
                        v.x = acc[mt][nt][half * 2 + 0] + bv.x;
                        v.y = acc[mt][nt][half * 2 + 1] + bv.y;
                        *(float2*)(orow + nt * 8 + nc) = v;
                    }
                }
            }
        }
    }
}

// ---------------- launch ----------------
extern "C" void kernel_launch(void* const* d_in, const int* in_sizes, int n_in,
                              void* d_out, int out_size) {
    const float* h_full = (const float*)d_in[0];
    const float* h_sub  = (const float*)d_in[1];
    const float* W1     = (const float*)d_in[2];
    const float* b1     = (const float*)d_in[3];
    const float* W2     = (const float*)d_in[4];
    const float* b2     = (const float*)d_in[5];
    const void*  idx    = d_in[6];
    float*       out    = (float*)d_out;

    const int dim   = in_sizes[3];
    const int Mrows = in_sizes[1] / dim;
    const int Nfull = in_sizes[0] / dim;

    static cudaStream_t sCopy = nullptr;
    static cudaEvent_t  evFork = nullptr, evJoin = nullptr;
    if (!sCopy) {
        cudaStreamCreateWithFlags(&sCopy, cudaStreamNonBlocking);
        cudaEventCreateWithFlags(&evFork, cudaEventDisableTiming);
        cudaEventCreateWithFlags(&evJoin, cudaEventDisableTiming);
    }

    cudaFuncSetAttribute(merge_gemm_fp16,
                         cudaFuncAttributeMaxDynamicSharedMemorySize, SM_TOTAL);

    // prep (stream 0)
    detect_idx_kernel<<<1, 1>>>(idx, Mrows, (long long)Nfull);
    convert_W<<<(256 * 512 + 255) / 256, 256>>>(W1, W2);
    const int maskWords = (Nfull + 15) / 16;
    clear_mask<<<(maskWords + 255) / 256, 256>>>(maskWords);
    set_mask<<<(Mrows + 255) / 256, 256>>>(idx, Mrows);

    // fork: masked copy on sCopy, GEMM on stream 0 (disjoint writes)
    cudaEventRecord(evFork, 0);
    cudaStreamWaitEvent(sCopy, evFork, 0);

    masked_copy<<<2048, 256, 0, sCopy>>>(h_full, out, Nfull);

    const int tiles = (Mrows + BM - 1) / BM;
    dim3 grid((unsigned)tiles, (unsigned)(dim / BN));
    merge_gemm_fp16<<<grid, THREADS, SM_TOTAL>>>(h_full, h_sub, b1, b2, idx,
                                                 out, Mrows);

    // join
    cudaEventRecord(evJoin, sCopy);
    cudaStreamWaitEvent(0, evJoin, 0);
}

// round 9
// speedup vs baseline: 3.5832x; 1.1581x over previous
#include <cuda_runtime.h>
#include <cuda_fp16.h>
#include <cstdint>

// ---------------------------------------------------------------------------
// NodeUnpool via fp16 HMMA (m16n8k16.f16, fp32 accumulate), single product:
//   out = h_full;  out[idx] = h_full[idx]@W1^T + b1 + h_sub@W2^T + b2
// C[M,256] = [h_full[idx] | h_sub] @ [W1 | W2]^T   (K = 512 concat)
//
// R9: BN=256 single N-pass (gather each A row once, halves gather traffic),
// 512-thread CTA, 16 warps (4x4 warp grid, 32x64 warp tile).
// Row-per-warp masked copy (mask check once per row, 512B coalesced moves)
// overlaps the GEMM on a second stream; writes are disjoint.
// ---------------------------------------------------------------------------

#define DIM      256
#define BM       128
#define BN       256
#define KC       64
#define THREADS  512
#define ROWB     144            // 64 halves = 128B + 16B pad (conflict-free)

// smem layout (bytes)
#define SM_ROWIDX 0             // int[128]
#define SM_BIAS   512           // float[256]
#define A_STAGE   (128 * ROWB)  // 18432
#define B_STAGE   (256 * ROWB)  // 36864
#define SM_A      2048          // 2 stages
#define SM_B      (SM_A + 2 * A_STAGE)      // 38912
#define SM_TOTAL  (SM_B + 2 * B_STAGE)      // 112640

#define MASK_CAP  (2u << 20)

__device__ int g_idx_is64;
__device__ __align__(16) __half g_Bw[256 * 512];          // [n][kcat] fp16
__device__ __align__(16) unsigned char g_mask[MASK_CAP];  // 1 = pooled row

// ---------------- helpers ----------------
__device__ __forceinline__ uint32_t smem_u32(const void* p) {
    uint32_t a;
    asm("{ .reg .u64 t; cvta.to.shared.u64 t, %1; cvt.u32.u64 %0, t; }"
        : "=r"(a) : "l"(p));
    return a;
}
__device__ __forceinline__ void cp_async16(uint32_t dst, const void* src) {
    asm volatile("cp.async.cg.shared.global [%0], [%1], 16;"
                 :: "r"(dst), "l"(src) : "memory");
}
__device__ __forceinline__ void cp_commit() {
    asm volatile("cp.async.commit_group;" ::: "memory");
}
__device__ __forceinline__ void cp_wait0() {
    asm volatile("cp.async.wait_group 0;" ::: "memory");
}
__device__ __forceinline__ void ldsm4(uint32_t* r, uint32_t addr) {
    asm volatile("ldmatrix.sync.aligned.m8n8.x4.shared.b16 {%0,%1,%2,%3}, [%4];"
                 : "=r"(r[0]), "=r"(r[1]), "=r"(r[2]), "=r"(r[3]) : "r"(addr));
}
__device__ __forceinline__ uint32_t lds32(uint32_t addr) {
    uint32_t v;
    asm volatile("ld.shared.b32 %0, [%1];" : "=r"(v) : "r"(addr));
    return v;
}
__device__ __forceinline__ void hmma(float* d, const uint32_t* a,
                                     uint32_t b0, uint32_t b1) {
    asm volatile(
        "mma.sync.aligned.m16n8k16.row.col.f32.f16.f16.f32 "
        "{%0,%1,%2,%3}, {%4,%5,%6,%7}, {%8,%9}, {%0,%1,%2,%3};"
        : "+f"(d[0]), "+f"(d[1]), "+f"(d[2]), "+f"(d[3])
        : "r"(a[0]), "r"(a[1]), "r"(a[2]), "r"(a[3]), "r"(b0), "r"(b1));
}

// ---------------- idx dtype detection ----------------
__device__ __forceinline__ long long load_idx(const void* idx, int r, int is64) {
    if (is64) return reinterpret_cast<const long long*>(idx)[r];
    return (long long)reinterpret_cast<const int*>(idx)[r];
}
__global__ void detect_idx_kernel(const void* idx, int Mrows, long long Nfull) {
    const long long* p64 = reinterpret_cast<const long long*>(idx);
    int n = Mrows / 2;
    if (n > 8) n = 8;
    bool ok64 = (n > 0);
    for (int i = 0; i < n; ++i) {
        long long v = p64[i];
        if (v < 0 || v >= Nfull) { ok64 = false; break; }
    }
    g_idx_is64 = ok64 ? 1 : 0;
}

// ---------------- mask clear / set ----------------
__global__ void clear_mask(int nWords) {
    int t = blockIdx.x * blockDim.x + threadIdx.x;
    uint4* p = reinterpret_cast<uint4*>(g_mask);
    if (t < nWords) p[t] = make_uint4(0, 0, 0, 0);
}
__global__ void set_mask(const void* __restrict__ idx, int Mrows) {
    int t = blockIdx.x * blockDim.x + threadIdx.x;
    if (t < Mrows) {
        long long g = load_idx(idx, t, g_idx_is64);
        g_mask[g] = 1;
    }
}

// ---------------- W -> fp16, [n][kcat] ----------------
__global__ void convert_W(const float* __restrict__ W1, const float* __restrict__ W2) {
    int t = blockIdx.x * blockDim.x + threadIdx.x;   // 256*512
    if (t >= 256 * 512) return;
    int n    = t >> 9;
    int kcat = t & 511;
    float x = (kcat < DIM) ? W1[n * DIM + kcat] : W2[n * DIM + (kcat - DIM)];
    g_Bw[t] = __float2half_rn(x);
}

// ---------------- masked row copy: one row per warp iteration ----------------
__global__ __launch_bounds__(256)
void masked_copy(const float* __restrict__ h_full,
                 float* __restrict__ out, int Nfull)
{
    const float4* in4  = reinterpret_cast<const float4*>(h_full);
    float4*       out4 = reinterpret_cast<float4*>(out);
    const int lane = threadIdx.x & 31;
    const int gw   = (int)((blockIdx.x * blockDim.x + threadIdx.x) >> 5);
    const int nw   = (int)((gridDim.x * blockDim.x) >> 5);
    for (int r = gw; r < Nfull; r += nw) {
        if (g_mask[r]) continue;                  // broadcast byte, 1 per row
        size_t base = (size_t)r * (DIM / 4);      // 64 float4 per row
        float4 v0 = in4[base + lane];
        float4 v1 = in4[base + 32 + lane];
        out4[base + lane]      = v0;
        out4[base + 32 + lane] = v1;
    }
}

// ---------------- main GEMM (fp16 HMMA, BN=256 single pass) ----------------
__global__ __launch_bounds__(THREADS, 1)
void merge_gemm_fp16(const float* __restrict__ h_full,
                     const float* __restrict__ h_sub,
                     const float* __restrict__ b1,
                     const float* __restrict__ b2,
                     const void*  __restrict__ idx,
                     float* __restrict__ out,
                     int Mrows)
{
    extern __shared__ __align__(16) char smem[];
    const uint32_t sbase = smem_u32(smem);

    const int tid   = threadIdx.x;
    const int wid   = tid >> 5;
    const int lid   = tid & 31;
    const int tileM = blockIdx.x * BM;
    const int warpM = (wid & 3) * 32;      // 4 warps in M
    const int warpN = (wid >> 2) * 64;     // 4 warp groups in N

    int*   rowidx = (int*)(smem + SM_ROWIDX);
    float* biasS  = (float*)(smem + SM_BIAS);

    const int is64 = g_idx_is64;
    if (tid < BM) {
        int m = tileM + tid;
        rowidx[tid] = (m < Mrows) ? (int)load_idx(idx, m, is64) : 0;
    }
    if (tid < DIM) biasS[tid] = b1[tid] + b2[tid];
    __syncthreads();

    // ---- B stage fill via cp.async: 256 rows x 128B -> 2048 x 16B segs
    auto issueB = [&](int c, int st) {
        uint32_t dbase = sbase + SM_B + st * B_STAGE;
#pragma unroll
        for (int j = 0; j < 4; ++j) {
            int id  = tid + j * THREADS;     // 0..2047
            int row = id >> 3;               // 0..255
            int seg = id & 7;                // 16B segment
            uint32_t dst = dbase + row * ROWB + seg * 16;
            const char* src = (const char*)g_Bw
                            + (((size_t)row << 9) + c * KC + seg * 8) * 2;
            cp_async16(dst, src);
        }
    };

    // ---- A chunk gather into regs: 2048 float4, 4 per thread
    auto loadA = [&](float4* dst, int c) {
        const bool fromFull = (c < 4);
        const int  kb = (c & 3) * KC;
#pragma unroll
        for (int j = 0; j < 4; ++j) {
            int id = tid + j * THREADS;      // 0..2047
            int r  = id >> 4;                // 0..127
            int c4 = (id & 15) << 2;         // 0..60
            const float* src;
            if (fromFull) {
                src = h_full + (size_t)rowidx[r] * DIM;
            } else {
                int m = tileM + r;
                if (m >= Mrows) m = Mrows - 1;
                src = h_sub + (size_t)m * DIM;
            }
            dst[j] = *(const float4*)(src + kb + c4);
        }
    };

    // ---- A regs -> fp16 smem (stage st)
    auto storeA = [&](const float4* v, int st) {
        uint32_t abase = (uint32_t)(SM_A + st * A_STAGE);
#pragma unroll
        for (int j = 0; j < 4; ++j) {
            int id = tid + j * THREADS;
            int r  = id >> 4;
            int c4 = (id & 15) << 2;
            float4 q = v[j];
            __half2 p01 = __floats2half2_rn(q.x, q.y);
            __half2 p23 = __floats2half2_rn(q.z, q.w);
            *(uint2*)(smem + abase + r * ROWB + c4 * 2) =
                make_uint2(*(uint32_t*)&p01, *(uint32_t*)&p23);
        }
    };

    float acc[2][8][4];
#pragma unroll
    for (int mt = 0; mt < 2; ++mt)
#pragma unroll
        for (int nt = 0; nt < 8; ++nt)
#pragma unroll
            for (int q = 0; q < 4; ++q) acc[mt][nt][q] = 0.f;

    // ---- compute one KC=64 chunk from stage st
    auto compute = [&](int st) {
        const uint32_t aB = sbase + SM_A + st * A_STAGE;
        const uint32_t bB = sbase + SM_B + st * B_STAGE;
#pragma unroll
        for (int kk = 0; kk < 4; ++kk) {
            uint32_t a[2][4];
#pragma unroll
            for (int mt = 0; mt < 2; ++mt) {
                uint32_t ra = (uint32_t)(warpM + mt * 16 + (lid & 15)) * ROWB
                            + (kk * 16 + (lid >> 4) * 8) * 2;
                ldsm4(a[mt], aB + ra);
            }
#pragma unroll
            for (int nt = 0; nt < 8; ++nt) {
                uint32_t rb = bB + (uint32_t)(warpN + nt * 8 + (lid >> 2)) * ROWB
                            + (kk * 16 + (lid & 3) * 2) * 2;
                uint32_t b0 = lds32(rb), b1v = lds32(rb + 16);
#pragma unroll
                for (int mt = 0; mt < 2; ++mt)
                    hmma(acc[mt][nt], a[mt], b0, b1v);
            }
        }
    };

    // ---- prologue: chunk 0 into stage 0
    float4 aPre[4];
    issueB(0, 0);
    cp_commit();
    loadA(aPre, 0);
    storeA(aPre, 0);
    cp_wait0();
    __syncthreads();

    // ---- main loop: one sync per chunk (A and B double-buffered)
#pragma unroll 1
    for (int c = 0; c < 8; ++c) {
        const int st = c & 1;
        if (c < 7) {
            issueB(c + 1, st ^ 1);
            cp_commit();
            loadA(aPre, c + 1);
        }
        compute(st);
        if (c < 7) {
            storeA(aPre, st ^ 1);
            cp_wait0();
        }
        __syncthreads();
    }

    // ---- epilogue: bias add + scatter
    {
        const int r0 = lid >> 2;
        const int nc = (lid & 3) * 2;
#pragma unroll
        for (int mt = 0; mt < 2; ++mt) {
#pragma unroll
            for (int half = 0; half < 2; ++half) {
                int row = warpM + mt * 16 + r0 + half * 8;
                int mg  = tileM + row;
                if (mg < Mrows) {
                    float* orow = out + (size_t)rowidx[row] * DIM + warpN;
#pragma unroll
                    for (int nt = 0; nt < 8; ++nt) {
                        float2 bv = *(const float2*)&biasS[warpN + nt * 8 + nc];
                        float2 v;
                        v.x = acc[mt][nt][half * 2 + 0] + bv.x;
                        v.y = acc[mt][nt][half * 2 + 1] + bv.y;
                        *(float2*)(orow + nt * 8 + nc) = v;
                    }
                }
            }
        }
    }
}

// ---------------- launch ----------------
extern "C" void kernel_launch(void* const* d_in, const int* in_sizes, int n_in,
                              void* d_out, int out_size) {
    const float* h_full = (const float*)d_in[0];
    const float* h_sub  = (const float*)d_in[1];
    const float* W1     = (const float*)d_in[2];
    const float* b1     = (const float*)d_in[3];
    const float* W2     = (const float*)d_in[4];
    const float* b2     = (const float*)d_in[5];
    const void*  idx    = d_in[6];
    float*       out    = (float*)d_out;

    const int dim   = in_sizes[3];
    const int Mrows = in_sizes[1] / dim;
    const int Nfull = in_sizes[0] / dim;

    static cudaStream_t sCopy = nullptr;
    static cudaEvent_t  evFork = nullptr, evJoin = nullptr;
    if (!sCopy) {
        cudaStreamCreateWithFlags(&sCopy, cudaStreamNonBlocking);
        cudaEventCreateWithFlags(&evFork, cudaEventDisableTiming);
        cudaEventCreateWithFlags(&evJoin, cudaEventDisableTiming);
    }

    cudaFuncSetAttribute(merge_gemm_fp16,
                         cudaFuncAttributeMaxDynamicSharedMemorySize, SM_TOTAL);

    // prep (stream 0)
    detect_idx_kernel<<<1, 1>>>(idx, Mrows, (long long)Nfull);
    convert_W<<<(256 * 512 + 255) / 256, 256>>>(W1, W2);
    const int maskWords = (Nfull + 15) / 16;
    clear_mask<<<(maskWords + 255) / 256, 256>>>(maskWords);
    set_mask<<<(Mrows + 255) / 256, 256>>>(idx, Mrows);

    // fork: masked copy on sCopy, GEMM on stream 0 (disjoint writes)
    cudaEventRecord(evFork, 0);
    cudaStreamWaitEvent(sCopy, evFork, 0);

    masked_copy<<<2048, 256, 0, sCopy>>>(h_full, out, Nfull);

    const int tiles = (Mrows + BM - 1) / BM;
    merge_gemm_fp16<<<tiles, THREADS, SM_TOTAL>>>(h_full, h_sub, b1, b2, idx,
                                                  out, Mrows);

    // join
    cudaEventRecord(evJoin, sCopy);
    cudaStreamWaitEvent(0, evJoin, 0);
}

// round 10
// speedup vs baseline: 3.6188x; 1.0099x over previous
#include <cuda_runtime.h>
#include <cuda_fp16.h>
#include <cstdint>

// ---------------------------------------------------------------------------
// NodeUnpool via fp16 HMMA (m16n8k16.f16, fp32 accumulate), single product:
//   out = h_full;  out[idx] = h_full[idx]@W1^T + b1 + h_sub@W2^T + b2
// C[M,256] = [h_full[idx] | h_sub] @ [W1 | W2]^T   (K = 512 concat)
//
// R10: prep chain parallelized across the two streams (clear_mask has no
// deps; set_mask waits only on detect; GEMM waits only on convert_W);
// streaming cache hints (.cs) on the once-touched bulk traffic.
// ---------------------------------------------------------------------------

#define DIM      256
#define BM       128
#define BN       256
#define KC       64
#define THREADS  512
#define ROWB     144            // 64 halves = 128B + 16B pad (conflict-free)

// smem layout (bytes)
#define SM_ROWIDX 0             // int[128]
#define SM_BIAS   512           // float[256]
#define A_STAGE   (128 * ROWB)  // 18432
#define B_STAGE   (256 * ROWB)  // 36864
#define SM_A      2048          // 2 stages
#define SM_B      (SM_A + 2 * A_STAGE)      // 38912
#define SM_TOTAL  (SM_B + 2 * B_STAGE)      // 112640

#define MASK_CAP  (2u << 20)

__device__ int g_idx_is64;
__device__ __align__(16) __half g_Bw[256 * 512];          // [n][kcat] fp16
__device__ __align__(16) unsigned char g_mask[MASK_CAP];  // 1 = pooled row

// ---------------- helpers ----------------
__device__ __forceinline__ uint32_t smem_u32(const void* p) {
    uint32_t a;
    asm("{ .reg .u64 t; cvta.to.shared.u64 t, %1; cvt.u32.u64 %0, t; }"
        : "=r"(a) : "l"(p));
    return a;
}
__device__ __forceinline__ void cp_async16(uint32_t dst, const void* src) {
    asm volatile("cp.async.cg.shared.global [%0], [%1], 16;"
                 :: "r"(dst), "l"(src) : "memory");
}
__device__ __forceinline__ void cp_commit() {
    asm volatile("cp.async.commit_group;" ::: "memory");
}
__device__ __forceinline__ void cp_wait0() {
    asm volatile("cp.async.wait_group 0;" ::: "memory");
}
__device__ __forceinline__ void ldsm4(uint32_t* r, uint32_t addr) {
    asm volatile("ldmatrix.sync.aligned.m8n8.x4.shared.b16 {%0,%1,%2,%3}, [%4];"
                 : "=r"(r[0]), "=r"(r[1]), "=r"(r[2]), "=r"(r[3]) : "r"(addr));
}
__device__ __forceinline__ uint32_t lds32(uint32_t addr) {
    uint32_t v;
    asm volatile("ld.shared.b32 %0, [%1];" : "=r"(v) : "r"(addr));
    return v;
}
__device__ __forceinline__ void hmma(float* d, const uint32_t* a,
                                     uint32_t b0, uint32_t b1) {
    asm volatile(
        "mma.sync.aligned.m16n8k16.row.col.f32.f16.f16.f32 "
        "{%0,%1,%2,%3}, {%4,%5,%6,%7}, {%8,%9}, {%0,%1,%2,%3};"
        : "+f"(d[0]), "+f"(d[1]), "+f"(d[2]), "+f"(d[3])
        : "r"(a[0]), "r"(a[1]), "r"(a[2]), "r"(a[3]), "r"(b0), "r"(b1));
}

// ---------------- idx dtype detection ----------------
__device__ __forceinline__ long long load_idx(const void* idx, int r, int is64) {
    if (is64) return reinterpret_cast<const long long*>(idx)[r];
    return (long long)reinterpret_cast<const int*>(idx)[r];
}
__global__ void detect_idx_kernel(const void* idx, int Mrows, long long Nfull) {
    const long long* p64 = reinterpret_cast<const long long*>(idx);
    int n = Mrows / 2;
    if (n > 8) n = 8;
    bool ok64 = (n > 0);
    for (int i = 0; i < n; ++i) {
        long long v = p64[i];
        if (v < 0 || v >= Nfull) { ok64 = false; break; }
    }
    g_idx_is64 = ok64 ? 1 : 0;
}

// ---------------- mask clear / set ----------------
__global__ void clear_mask(int nWords) {
    int t = blockIdx.x * blockDim.x + threadIdx.x;
    uint4* p = reinterpret_cast<uint4*>(g_mask);
    if (t < nWords) p[t] = make_uint4(0, 0, 0, 0);
}
__global__ void set_mask(const void* __restrict__ idx, int Mrows) {
    int t = blockIdx.x * blockDim.x + threadIdx.x;
    if (t < Mrows) {
        long long g = load_idx(idx, t, g_idx_is64);
        g_mask[g] = 1;
    }
}

// ---------------- W -> fp16, [n][kcat] ----------------
__global__ void convert_W(const float* __restrict__ W1, const float* __restrict__ W2) {
    int t = blockIdx.x * blockDim.x + threadIdx.x;   // 256*512
    if (t >= 256 * 512) return;
    int n    = t >> 9;
    int kcat = t & 511;
    float x = (kcat < DIM) ? W1[n * DIM + kcat] : W2[n * DIM + (kcat - DIM)];
    g_Bw[t] = __float2half_rn(x);
}

// ---------------- masked row copy: one row per warp iteration ----------------
__global__ __launch_bounds__(256)
void masked_copy(const float* __restrict__ h_full,
                 float* __restrict__ out, int Nfull)
{
    const float4* in4  = reinterpret_cast<const float4*>(h_full);
    float4*       out4 = reinterpret_cast<float4*>(out);
    const int lane = threadIdx.x & 31;
    const int gw   = (int)((blockIdx.x * blockDim.x + threadIdx.x) >> 5);
    const int nw   = (int)((gridDim.x * blockDim.x) >> 5);
    for (int r = gw; r < Nfull; r += nw) {
        if (g_mask[r]) continue;                  // broadcast byte, 1 per row
        size_t base = (size_t)r * (DIM / 4);      // 64 float4 per row
        float4 v0 = __ldcs(&in4[base + lane]);
        float4 v1 = __ldcs(&in4[base + 32 + lane]);
        __stcs(&out4[base + lane], v0);
        __stcs(&out4[base + 32 + lane], v1);
    }
}

// ---------------- main GEMM (fp16 HMMA, BN=256 single pass) ----------------
__global__ __launch_bounds__(THREADS, 1)
void merge_gemm_fp16(const float* __restrict__ h_full,
                     const float* __restrict__ h_sub,
                     const float* __restrict__ b1,
                     const float* __restrict__ b2,
                     const void*  __restrict__ idx,
                     float* __restrict__ out,
                     int Mrows)
{
    extern __shared__ __align__(16) char smem[];
    const uint32_t sbase = smem_u32(smem);

    const int tid   = threadIdx.x;
    const int wid   = tid >> 5;
    const int lid   = tid & 31;
    const int tileM = blockIdx.x * BM;
    const int warpM = (wid & 3) * 32;      // 4 warps in M
    const int warpN = (wid >> 2) * 64;     // 4 warp groups in N

    int*   rowidx = (int*)(smem + SM_ROWIDX);
    float* biasS  = (float*)(smem + SM_BIAS);

    const int is64 = g_idx_is64;
    if (tid < BM) {
        int m = tileM + tid;
        rowidx[tid] = (m < Mrows) ? (int)load_idx(idx, m, is64) : 0;
    }
    if (tid < DIM) biasS[tid] = b1[tid] + b2[tid];
    __syncthreads();

    // ---- B stage fill via cp.async: 256 rows x 128B -> 2048 x 16B segs
    auto issueB = [&](int c, int st) {
        uint32_t dbase = sbase + SM_B + st * B_STAGE;
#pragma unroll
        for (int j = 0; j < 4; ++j) {
            int id  = tid + j * THREADS;     // 0..2047
            int row = id >> 3;               // 0..255
            int seg = id & 7;                // 16B segment
            uint32_t dst = dbase + row * ROWB + seg * 16;
            const char* src = (const char*)g_Bw
                            + (((size_t)row << 9) + c * KC + seg * 8) * 2;
            cp_async16(dst, src);
        }
    };

    // ---- A chunk gather into regs: 2048 float4, 4 per thread
    auto loadA = [&](float4* dst, int c) {
        const bool fromFull = (c < 4);
        const int  kb = (c & 3) * KC;
#pragma unroll
        for (int j = 0; j < 4; ++j) {
            int id = tid + j * THREADS;      // 0..2047
            int r  = id >> 4;                // 0..127
            int c4 = (id & 15) << 2;         // 0..60
            const float* src;
            if (fromFull) {
                src = h_full + (size_t)rowidx[r] * DIM;
            } else {
                int m = tileM + r;
                if (m >= Mrows) m = Mrows - 1;
                src = h_sub + (size_t)m * DIM;
            }
            dst[j] = __ldcs((const float4*)(src + kb + c4));
        }
    };

    // ---- A regs -> fp16 smem (stage st)
    auto storeA = [&](const float4* v, int st) {
        uint32_t abase = (uint32_t)(SM_A + st * A_STAGE);
#pragma unroll
        for (int j = 0; j < 4; ++j) {
            int id = tid + j * THREADS;
            int r  = id >> 4;
            int c4 = (id & 15) << 2;
            float4 q = v[j];
            __half2 p01 = __floats2half2_rn(q.x, q.y);
            __half2 p23 = __floats2half2_rn(q.z, q.w);
            *(uint2*)(smem + abase + r * ROWB + c4 * 2) =
                make_uint2(*(uint32_t*)&p01, *(uint32_t*)&p23);
        }
    };

    float acc[2][8][4];
#pragma unroll
    for (int mt = 0; mt < 2; ++mt)
#pragma unroll
        for (int nt = 0; nt < 8; ++nt)
#pragma unroll
            for (int q = 0; q < 4; ++q) acc[mt][nt][q] = 0.f;

    // ---- compute one KC=64 chunk from stage st
    auto compute = [&](int st) {
        const uint32_t aB = sbase + SM_A + st * A_STAGE;
        const uint32_t bB = sbase + SM_B + st * B_STAGE;
#pragma unroll
        for (int kk = 0; kk < 4; ++kk) {
            uint32_t a[2][4];
#pragma unroll
            for (int mt = 0; mt < 2; ++mt) {
                uint32_t ra = (uint32_t)(warpM + mt * 16 + (lid & 15)) * ROWB
                            + (kk * 16 + (lid >> 4) * 8) * 2;
                ldsm4(a[mt], aB + ra);
            }
#pragma unroll
            for (int nt = 0; nt < 8; ++nt) {
                uint32_t rb = bB + (uint32_t)(warpN + nt * 8 + (lid >> 2)) * ROWB
                            + (kk * 16 + (lid & 3) * 2) * 2;
                uint32_t b0 = lds32(rb), b1v = lds32(rb + 16);
#pragma unroll
                for (int mt = 0; mt < 2; ++mt)
                    hmma(acc[mt][nt], a[mt], b0, b1v);
            }
        }
    };

    // ---- prologue: chunk 0 into stage 0
    float4 aPre[4];
    issueB(0, 0);
    cp_commit();
    loadA(aPre, 0);
    storeA(aPre, 0);
    cp_wait0();
    __syncthreads();

    // ---- main loop: one sync per chunk (A and B double-buffered)
#pragma unroll 1
    for (int c = 0; c < 8; ++c) {
        const int st = c & 1;
        if (c < 7) {
            issueB(c + 1, st ^ 1);
            cp_commit();
            loadA(aPre, c + 1);
        }
        compute(st);
        if (c < 7) {
            storeA(aPre, st ^ 1);
            cp_wait0();
        }
        __syncthreads();
    }

    // ---- epilogue: bias add + scatter (streaming stores)
    {
        const int r0 = lid >> 2;
        const int nc = (lid & 3) * 2;
#pragma unroll
        for (int mt = 0; mt < 2; ++mt) {
#pragma unroll
            for (int half = 0; half < 2; ++half) {
                int row = warpM + mt * 16 + r0 + half * 8;
                int mg  = tileM + row;
                if (mg < Mrows) {
                    float* orow = out + (size_t)rowidx[row] * DIM + warpN;
#pragma unroll
                    for (int nt = 0; nt < 8; ++nt) {
                        float2 bv = *(const float2*)&biasS[warpN + nt * 8 + nc];
                        float2 v;
                        v.x = acc[mt][nt][half * 2 + 0] + bv.x;
                        v.y = acc[mt][nt][half * 2 + 1] + bv.y;
                        __stcs((float2*)(orow + nt * 8 + nc), v);
                    }
                }
            }
        }
    }
}

// ---------------- launch ----------------
extern "C" void kernel_launch(void* const* d_in, const int* in_sizes, int n_in,
                              void* d_out, int out_size) {
    const float* h_full = (const float*)d_in[0];
    const float* h_sub  = (const float*)d_in[1];
    const float* W1     = (const float*)d_in[2];
    const float* b1     = (const float*)d_in[3];
    const float* W2     = (const float*)d_in[4];
    const float* b2     = (const float*)d_in[5];
    const void*  idx    = d_in[6];
    float*       out    = (float*)d_out;

    const int dim   = in_sizes[3];
    const int Mrows = in_sizes[1] / dim;
    const int Nfull = in_sizes[0] / dim;

    static cudaStream_t sCopy = nullptr;
    static cudaEvent_t  evDet = nullptr, evJoin = nullptr;
    if (!sCopy) {
        cudaStreamCreateWithFlags(&sCopy, cudaStreamNonBlocking);
        cudaEventCreateWithFlags(&evDet, cudaEventDisableTiming);
        cudaEventCreateWithFlags(&evJoin, cudaEventDisableTiming);
    }

    cudaFuncSetAttribute(merge_gemm_fp16,
                         cudaFuncAttributeMaxDynamicSharedMemorySize, SM_TOTAL);

    // ---- prep, parallel across streams ----
    // sCopy: clear_mask (no deps)           stream0: detect -> convert_W
    const int maskWords = (Nfull + 15) / 16;
    clear_mask<<<(maskWords + 255) / 256, 256, 0, sCopy>>>(maskWords);

    detect_idx_kernel<<<1, 1>>>(idx, Mrows, (long long)Nfull);
    cudaEventRecord(evDet, 0);
    convert_W<<<(256 * 512 + 255) / 256, 256>>>(W1, W2);

    // sCopy: set_mask after detect, then the bulk masked copy
    cudaStreamWaitEvent(sCopy, evDet, 0);
    set_mask<<<(Mrows + 255) / 256, 256, 0, sCopy>>>(idx, Mrows);
    masked_copy<<<2960, 256, 0, sCopy>>>(h_full, out, Nfull);

    // stream0: GEMM right after convert_W (disjoint writes vs copy)
    const int tiles = (Mrows + BM - 1) / BM;
    merge_gemm_fp16<<<tiles, THREADS, SM_TOTAL>>>(h_full, h_sub, b1, b2, idx,
                                                  out, Mrows);

    // join
    cudaEventRecord(evJoin, sCopy);
    cudaStreamWaitEvent(0, evJoin, 0);
}

// round 11
// speedup vs baseline: 3.6260x; 1.0020x over previous
#include <cuda_runtime.h>
#include <cuda_fp16.h>
#include <cstdint>

// ---------------------------------------------------------------------------
// NodeUnpool via fp16 HMMA (m16n8k16.f16, fp32 accumulate), single product:
//   out = h_full;  out[idx] = h_full[idx]@W1^T + b1 + h_sub@W2^T + b2
// C[M,256] = [h_full[idx] | h_sub] @ [W1 | W2]^T   (K = 512 concat)
//
// R11: masked copy software-pipelines the mask load (prefetch next row's
// mask before processing the current row) so the per-row critical path is
// one LDG latency, not two. Copy then truly hides under the HMMA-bound GEMM.
// ---------------------------------------------------------------------------

#define DIM      256
#define BM       128
#define BN       256
#define KC       64
#define THREADS  512
#define ROWB     144            // 64 halves = 128B + 16B pad (conflict-free)

// smem layout (bytes)
#define SM_ROWIDX 0             // int[128]
#define SM_BIAS   512           // float[256]
#define A_STAGE   (128 * ROWB)  // 18432
#define B_STAGE   (256 * ROWB)  // 36864
#define SM_A      2048          // 2 stages
#define SM_B      (SM_A + 2 * A_STAGE)      // 38912
#define SM_TOTAL  (SM_B + 2 * B_STAGE)      // 112640

#define MASK_CAP  (2u << 20)

__device__ int g_idx_is64;
__device__ __align__(16) __half g_Bw[256 * 512];          // [n][kcat] fp16
__device__ __align__(16) unsigned char g_mask[MASK_CAP];  // 1 = pooled row

// ---------------- helpers ----------------
__device__ __forceinline__ uint32_t smem_u32(const void* p) {
    uint32_t a;
    asm("{ .reg .u64 t; cvta.to.shared.u64 t, %1; cvt.u32.u64 %0, t; }"
        : "=r"(a) : "l"(p));
    return a;
}
__device__ __forceinline__ void cp_async16(uint32_t dst, const void* src) {
    asm volatile("cp.async.cg.shared.global [%0], [%1], 16;"
                 :: "r"(dst), "l"(src) : "memory");
}
__device__ __forceinline__ void cp_commit() {
    asm volatile("cp.async.commit_group;" ::: "memory");
}
__device__ __forceinline__ void cp_wait0() {
    asm volatile("cp.async.wait_group 0;" ::: "memory");
}
__device__ __forceinline__ void ldsm4(uint32_t* r, uint32_t addr) {
    asm volatile("ldmatrix.sync.aligned.m8n8.x4.shared.b16 {%0,%1,%2,%3}, [%4];"
                 : "=r"(r[0]), "=r"(r[1]), "=r"(r[2]), "=r"(r[3]) : "r"(addr));
}
__device__ __forceinline__ uint32_t lds32(uint32_t addr) {
    uint32_t v;
    asm volatile("ld.shared.b32 %0, [%1];" : "=r"(v) : "r"(addr));
    return v;
}
__device__ __forceinline__ void hmma(float* d, const uint32_t* a,
                                     uint32_t b0, uint32_t b1) {
    asm volatile(
        "mma.sync.aligned.m16n8k16.row.col.f32.f16.f16.f32 "
        "{%0,%1,%2,%3}, {%4,%5,%6,%7}, {%8,%9}, {%0,%1,%2,%3};"
        : "+f"(d[0]), "+f"(d[1]), "+f"(d[2]), "+f"(d[3])
        : "r"(a[0]), "r"(a[1]), "r"(a[2]), "r"(a[3]), "r"(b0), "r"(b1));
}

// ---------------- idx dtype detection ----------------
__device__ __forceinline__ long long load_idx(const void* idx, int r, int is64) {
    if (is64) return reinterpret_cast<const long long*>(idx)[r];
    return (long long)reinterpret_cast<const int*>(idx)[r];
}
__global__ void detect_idx_kernel(const void* idx, int Mrows, long long Nfull) {
    const long long* p64 = reinterpret_cast<const long long*>(idx);
    int n = Mrows / 2;
    if (n > 8) n = 8;
    bool ok64 = (n > 0);
    for (int i = 0; i < n; ++i) {
        long long v = p64[i];
        if (v < 0 || v >= Nfull) { ok64 = false; break; }
    }
    g_idx_is64 = ok64 ? 1 : 0;
}

// ---------------- mask clear / set ----------------
__global__ void clear_mask(int nWords) {
    int t = blockIdx.x * blockDim.x + threadIdx.x;
    uint4* p = reinterpret_cast<uint4*>(g_mask);
    if (t < nWords) p[t] = make_uint4(0, 0, 0, 0);
}
__global__ void set_mask(const void* __restrict__ idx, int Mrows) {
    int t = blockIdx.x * blockDim.x + threadIdx.x;
    if (t < Mrows) {
        long long g = load_idx(idx, t, g_idx_is64);
        g_mask[g] = 1;
    }
}

// ---------------- W -> fp16, [n][kcat] ----------------
__global__ void convert_W(const float* __restrict__ W1, const float* __restrict__ W2) {
    int t = blockIdx.x * blockDim.x + threadIdx.x;   // 256*512
    if (t >= 256 * 512) return;
    int n    = t >> 9;
    int kcat = t & 511;
    float x = (kcat < DIM) ? W1[n * DIM + kcat] : W2[n * DIM + (kcat - DIM)];
    g_Bw[t] = __float2half_rn(x);
}

// ---------------- masked row copy with mask software pipeline ----------------
__global__ __launch_bounds__(256)
void masked_copy(const float* __restrict__ h_full,
                 float* __restrict__ out, int Nfull)
{
    const float4* in4  = reinterpret_cast<const float4*>(h_full);
    float4*       out4 = reinterpret_cast<float4*>(out);
    const int lane = threadIdx.x & 31;
    const int gw   = (int)((blockIdx.x * blockDim.x + threadIdx.x) >> 5);
    const int nw   = (int)((gridDim.x * blockDim.x) >> 5);

    int r = gw;
    unsigned int m = (r < Nfull) ? (unsigned int)g_mask[r] : 1u;
    while (r < Nfull) {
        const int rn = r + nw;
        // prefetch next row's mask: its latency hides under this row's copy
        unsigned int mn = (rn < Nfull) ? (unsigned int)g_mask[rn] : 1u;
        if (!m) {
            size_t base = (size_t)r << 6;          // 64 float4 per row
            float4 v0 = __ldcs(&in4[base + lane]);
            float4 v1 = __ldcs(&in4[base + 32 + lane]);
            __stcs(&out4[base + lane], v0);
            __stcs(&out4[base + 32 + lane], v1);
        }
        r = rn;
        m = mn;
    }
}

// ---------------- main GEMM (fp16 HMMA, BN=256 single pass) ----------------
__global__ __launch_bounds__(THREADS, 1)
void merge_gemm_fp16(const float* __restrict__ h_full,
                     const float* __restrict__ h_sub,
                     const float* __restrict__ b1,
                     const float* __restrict__ b2,
                     const void*  __restrict__ idx,
                     float* __restrict__ out,
                     int Mrows)
{
    extern __shared__ __align__(16) char smem[];
    const uint32_t sbase = smem_u32(smem);

    const int tid   = threadIdx.x;
    const int wid   = tid >> 5;
    const int lid   = tid & 31;
    const int tileM = blockIdx.x * BM;
    const int warpM = (wid & 3) * 32;      // 4 warps in M
    const int warpN = (wid >> 2) * 64;     // 4 warp groups in N

    int*   rowidx = (int*)(smem + SM_ROWIDX);
    float* biasS  = (float*)(smem + SM_BIAS);

    const int is64 = g_idx_is64;
    if (tid < BM) {
        int m = tileM + tid;
        rowidx[tid] = (m < Mrows) ? (int)load_idx(idx, m, is64) : 0;
    }
    if (tid < DIM) biasS[tid] = b1[tid] + b2[tid];
    __syncthreads();

    // ---- B stage fill via cp.async: 256 rows x 128B -> 2048 x 16B segs
    auto issueB = [&](int c, int st) {
        uint32_t dbase = sbase + SM_B + st * B_STAGE;
#pragma unroll
        for (int j = 0; j < 4; ++j) {
            int id  = tid + j * THREADS;     // 0..2047
            int row = id >> 3;               // 0..255
            int seg = id & 7;                // 16B segment
            uint32_t dst = dbase + row * ROWB + seg * 16;
            const char* src = (const char*)g_Bw
                            + (((size_t)row << 9) + c * KC + seg * 8) * 2;
            cp_async16(dst, src);
        }
    };

    // ---- A chunk gather into regs: 2048 float4, 4 per thread
    auto loadA = [&](float4* dst, int c) {
        const bool fromFull = (c < 4);
        const int  kb = (c & 3) * KC;
#pragma unroll
        for (int j = 0; j < 4; ++j) {
            int id = tid + j * THREADS;      // 0..2047
            int r  = id >> 4;                // 0..127
            int c4 = (id & 15) << 2;         // 0..60
            const float* src;
            if (fromFull) {
                src = h_full + (size_t)rowidx[r] * DIM;
            } else {
                int m = tileM + r;
                if (m >= Mrows) m = Mrows - 1;
                src = h_sub + (size_t)m * DIM;
            }
            dst[j] = __ldcs((const float4*)(src + kb + c4));
        }
    };

    // ---- A regs -> fp16 smem (stage st)
    auto storeA = [&](const float4* v, int st) {
        uint32_t abase = (uint32_t)(SM_A + st * A_STAGE);
#pragma unroll
        for (int j = 0; j < 4; ++j) {
            int id = tid + j * THREADS;
            int r  = id >> 4;
            int c4 = (id & 15) << 2;
            float4 q = v[j];
            __half2 p01 = __floats2half2_rn(q.x, q.y);
            __half2 p23 = __floats2half2_rn(q.z, q.w);
            *(uint2*)(smem + abase + r * ROWB + c4 * 2) =
                make_uint2(*(uint32_t*)&p01, *(uint32_t*)&p23);
        }
    };

    float acc[2][8][4];
#pragma unroll
    for (int mt = 0; mt < 2; ++mt)
#pragma unroll
        for (int nt = 0; nt < 8; ++nt)
#pragma unroll
            for (int q = 0; q < 4; ++q) acc[mt][nt][q] = 0.f;

    // ---- compute one KC=64 chunk from stage st
    auto compute = [&](int st) {
        const uint32_t aB = sbase + SM_A + st * A_STAGE;
        const uint32_t bB = sbase + SM_B + st * B_STAGE;
#pragma unroll
        for (int kk = 0; kk < 4; ++kk) {
            uint32_t a[2][4];
#pragma unroll
            for (int mt = 0; mt < 2; ++mt) {
                uint32_t ra = (uint32_t)(warpM + mt * 16 + (lid & 15)) * ROWB
                            + (kk * 16 + (lid >> 4) * 8) * 2;
                ldsm4(a[mt], aB + ra);
            }
#pragma unroll
            for (int nt = 0; nt < 8; ++nt) {
                uint32_t rb = bB + (uint32_t)(warpN + nt * 8 + (lid >> 2)) * ROWB
                            + (kk * 16 + (lid & 3) * 2) * 2;
                uint32_t b0 = lds32(rb), b1v = lds32(rb + 16);
#pragma unroll
                for (int mt = 0; mt < 2; ++mt)
                    hmma(acc[mt][nt], a[mt], b0, b1v);
            }
        }
    };

    // ---- prologue: chunk 0 into stage 0
    float4 aPre[4];
    issueB(0, 0);
    cp_commit();
    loadA(aPre, 0);
    storeA(aPre, 0);
    cp_wait0();
    __syncthreads();

    // ---- main loop: one sync per chunk (A and B double-buffered)
#pragma unroll 1
    for (int c = 0; c < 8; ++c) {
        const int st = c & 1;
        if (c < 7) {
            issueB(c + 1, st ^ 1);
            cp_commit();
            loadA(aPre, c + 1);
        }
        compute(st);
        if (c < 7) {
            storeA(aPre, st ^ 1);
            cp_wait0();
        }
        __syncthreads();
    }

    // ---- epilogue: bias add + scatter (streaming stores)
    {
        const int r0 = lid >> 2;
        const int nc = (lid & 3) * 2;
#pragma unroll
        for (int mt = 0; mt < 2; ++mt) {
#pragma unroll
            for (int half = 0; half < 2; ++half) {
                int row = warpM + mt * 16 + r0 + half * 8;
                int mg  = tileM + row;
                if (mg < Mrows) {
                    float* orow = out + (size_t)rowidx[row] * DIM + warpN;
#pragma unroll
                    for (int nt = 0; nt < 8; ++nt) {
                        float2 bv = *(const float2*)&biasS[warpN + nt * 8 + nc];
                        float2 v;
                        v.x = acc[mt][nt][half * 2 + 0] + bv.x;
                        v.y = acc[mt][nt][half * 2 + 1] + bv.y;
                        __stcs((float2*)(orow + nt * 8 + nc), v);
                    }
                }
            }
        }
    }
}

// ---------------- launch ----------------
extern "C" void kernel_launch(void* const* d_in, const int* in_sizes, int n_in,
                              void* d_out, int out_size) {
    const float* h_full = (const float*)d_in[0];
    const float* h_sub  = (const float*)d_in[1];
    const float* W1     = (const float*)d_in[2];
    const float* b1     = (const float*)d_in[3];
    const float* W2     = (const float*)d_in[4];
    const float* b2     = (const float*)d_in[5];
    const void*  idx    = d_in[6];
    float*       out    = (float*)d_out;

    const int dim   = in_sizes[3];
    const int Mrows = in_sizes[1] / dim;
    const int Nfull = in_sizes[0] / dim;

    static cudaStream_t sCopy = nullptr;
    static cudaEvent_t  evDet = nullptr, evJoin = nullptr;
    if (!sCopy) {
        cudaStreamCreateWithFlags(&sCopy, cudaStreamNonBlocking);
        cudaEventCreateWithFlags(&evDet, cudaEventDisableTiming);
        cudaEventCreateWithFlags(&evJoin, cudaEventDisableTiming);
    }

    cudaFuncSetAttribute(merge_gemm_fp16,
                         cudaFuncAttributeMaxDynamicSharedMemorySize, SM_TOTAL);

    // ---- prep, parallel across streams ----
    const int maskWords = (Nfull + 15) / 16;
    clear_mask<<<(maskWords + 255) / 256, 256, 0, sCopy>>>(maskWords);

    detect_idx_kernel<<<1, 1>>>(idx, Mrows, (long long)Nfull);
    cudaEventRecord(evDet, 0);
    convert_W<<<(256 * 512 + 255) / 256, 256>>>(W1, W2);

    cudaStreamWaitEvent(sCopy, evDet, 0);
    set_mask<<<(Mrows + 255) / 256, 256, 0, sCopy>>>(idx, Mrows);
    masked_copy<<<2960, 256, 0, sCopy>>>(h_full, out, Nfull);

    const int tiles = (Mrows + BM - 1) / BM;
    merge_gemm_fp16<<<tiles, THREADS, SM_TOTAL>>>(h_full, h_sub, b1, b2, idx,
                                                  out, Mrows);

    cudaEventRecord(evJoin, sCopy);
    cudaStreamWaitEvent(0, evJoin, 0);
}

// round 12
// speedup vs baseline: 3.9087x; 1.0780x over previous
#include <cuda_runtime.h>
#include <cuda_fp16.h>
#include <cstdint>

// ---------------------------------------------------------------------------
// NodeUnpool via fp16 HMMA (m16n8k16.f16, fp32 accumulate), single product,
// with the bulk row-copy INTERLEAVED INTO the GEMM CTA (R12):
//   out = h_full;  out[idx] = h_full[idx]@W1^T + b1 + h_sub@W2^T + b2
// C[M,256] = [h_full[idx] | h_sub] @ [W1 | W2]^T   (K = 512 concat)
//
// Why: a 512-thread/128-reg GEMM CTA consumes the whole SM register file, so
// a separate copy kernel can never co-reside -> streams serialized. Weaving
// the copy into the K-loop (loads before each compute half, stores after)
// overlaps copy DRAM traffic with HMMA by construction.
// ---------------------------------------------------------------------------

#define DIM      256
#define BM       128
#define BN       256
#define KC       64
#define THREADS  512
#define ROWB     144            // 64 halves = 128B + 16B pad (conflict-free)

// smem layout (bytes)
#define SM_ROWIDX 0             // int[128]
#define SM_BIAS   512           // float[256]
#define SM_MASK   1536          // uchar[1024] copy-slice masks
#define A_STAGE   (128 * ROWB)  // 18432
#define B_STAGE   (256 * ROWB)  // 36864
#define SM_A      2560          // 2 stages
#define SM_B      (SM_A + 2 * A_STAGE)      // 39424
#define SM_TOTAL  (SM_B + 2 * B_STAGE)      // 113152

#define MASK_CAP  (2u << 20)

__device__ int g_idx_is64;
__device__ __align__(16) __half g_Bw[256 * 512];          // [n][kcat] fp16
__device__ __align__(16) unsigned char g_mask[MASK_CAP];  // 1 = pooled row

// ---------------- helpers ----------------
__device__ __forceinline__ uint32_t smem_u32(const void* p) {
    uint32_t a;
    asm("{ .reg .u64 t; cvta.to.shared.u64 t, %1; cvt.u32.u64 %0, t; }"
        : "=r"(a) : "l"(p));
    return a;
}
__device__ __forceinline__ void cp_async16(uint32_t dst, const void* src) {
    asm volatile("cp.async.cg.shared.global [%0], [%1], 16;"
                 :: "r"(dst), "l"(src) : "memory");
}
__device__ __forceinline__ void cp_commit() {
    asm volatile("cp.async.commit_group;" ::: "memory");
}
__device__ __forceinline__ void cp_wait0() {
    asm volatile("cp.async.wait_group 0;" ::: "memory");
}
__device__ __forceinline__ void ldsm4(uint32_t* r, uint32_t addr) {
    asm volatile("ldmatrix.sync.aligned.m8n8.x4.shared.b16 {%0,%1,%2,%3}, [%4];"
                 : "=r"(r[0]), "=r"(r[1]), "=r"(r[2]), "=r"(r[3]) : "r"(addr));
}
__device__ __forceinline__ uint32_t lds32(uint32_t addr) {
    uint32_t v;
    asm volatile("ld.shared.b32 %0, [%1];" : "=r"(v) : "r"(addr));
    return v;
}
__device__ __forceinline__ void hmma(float* d, const uint32_t* a,
                                     uint32_t b0, uint32_t b1) {
    asm volatile(
        "mma.sync.aligned.m16n8k16.row.col.f32.f16.f16.f32 "
        "{%0,%1,%2,%3}, {%4,%5,%6,%7}, {%8,%9}, {%0,%1,%2,%3};"
        : "+f"(d[0]), "+f"(d[1]), "+f"(d[2]), "+f"(d[3])
        : "r"(a[0]), "r"(a[1]), "r"(a[2]), "r"(a[3]), "r"(b0), "r"(b1));
}

// ---------------- idx dtype detection ----------------
__device__ __forceinline__ long long load_idx(const void* idx, int r, int is64) {
    if (is64) return reinterpret_cast<const long long*>(idx)[r];
    return (long long)reinterpret_cast<const int*>(idx)[r];
}
__global__ void detect_idx_kernel(const void* idx, int Mrows, long long Nfull) {
    const long long* p64 = reinterpret_cast<const long long*>(idx);
    int n = Mrows / 2;
    if (n > 8) n = 8;
    bool ok64 = (n > 0);
    for (int i = 0; i < n; ++i) {
        long long v = p64[i];
        if (v < 0 || v >= Nfull) { ok64 = false; break; }
    }
    g_idx_is64 = ok64 ? 1 : 0;
}

// ---------------- mask clear / set ----------------
__global__ void clear_mask(int nWords) {
    int t = blockIdx.x * blockDim.x + threadIdx.x;
    uint4* p = reinterpret_cast<uint4*>(g_mask);
    if (t < nWords) p[t] = make_uint4(0, 0, 0, 0);
}
__global__ void set_mask(const void* __restrict__ idx, int Mrows) {
    int t = blockIdx.x * blockDim.x + threadIdx.x;
    if (t < Mrows) {
        long long g = load_idx(idx, t, g_idx_is64);
        g_mask[g] = 1;
    }
}

// ---------------- W -> fp16, [n][kcat] ----------------
__global__ void convert_W(const float* __restrict__ W1, const float* __restrict__ W2) {
    int t = blockIdx.x * blockDim.x + threadIdx.x;   // 256*512
    if (t >= 256 * 512) return;
    int n    = t >> 9;
    int kcat = t & 511;
    float x = (kcat < DIM) ? W1[n * DIM + kcat] : W2[n * DIM + (kcat - DIM)];
    g_Bw[t] = __float2half_rn(x);
}

// ---------------- fused GEMM + interleaved masked copy ----------------
__global__ __launch_bounds__(THREADS, 1)
void merge_gemm_fp16(const float* __restrict__ h_full,
                     const float* __restrict__ h_sub,
                     const float* __restrict__ b1,
                     const float* __restrict__ b2,
                     const void*  __restrict__ idx,
                     float* __restrict__ out,
                     int Mrows, int Nfull, int rowsPer)
{
    extern __shared__ __align__(16) char smem[];
    const uint32_t sbase = smem_u32(smem);

    const int tid   = threadIdx.x;
    const int wid   = tid >> 5;
    const int lid   = tid & 31;
    const int tileM = blockIdx.x * BM;
    const int warpM = (wid & 3) * 32;      // 4 warps in M
    const int warpN = (wid >> 2) * 64;     // 4 warp groups in N

    int*           rowidx = (int*)(smem + SM_ROWIDX);
    float*         biasS  = (float*)(smem + SM_BIAS);
    unsigned char* maskS  = (unsigned char*)(smem + SM_MASK);

    // ---- copy slice for this CTA
    const int rows0   = blockIdx.x * rowsPer;
    const int rcChunk = min(64, (rowsPer + 7) / 8);   // rows per K-chunk
    const int halfR   = (rcChunk + 1) / 2;            // rows per group (<=32)

    const int is64 = g_idx_is64;
    if (tid < BM) {
        int m = tileM + tid;
        rowidx[tid] = (m < Mrows) ? (int)load_idx(idx, m, is64) : 0;
    }
    if (tid < DIM) biasS[tid] = b1[tid] + b2[tid];
    // stage copy-slice masks (<=1024 rows)
    {
        int rl = tid;                                  // 0..511
        int r0 = rows0 + rl;
        maskS[rl] = (rl < rowsPer && r0 < Nfull) ? g_mask[r0] : 1;
        rl += THREADS;
        r0 += THREADS;
        if (rl < 1024) maskS[rl] = (rl < rowsPer && r0 < Nfull) ? g_mask[r0] : 1;
    }
    __syncthreads();

    // ---- B stage fill via cp.async: 256 rows x 128B -> 2048 x 16B segs
    auto issueB = [&](int c, int st) {
        uint32_t dbase = sbase + SM_B + st * B_STAGE;
#pragma unroll
        for (int j = 0; j < 4; ++j) {
            int id  = tid + j * THREADS;     // 0..2047
            int row = id >> 3;               // 0..255
            int seg = id & 7;                // 16B segment
            uint32_t dst = dbase + row * ROWB + seg * 16;
            const char* src = (const char*)g_Bw
                            + (((size_t)row << 9) + c * KC + seg * 8) * 2;
            cp_async16(dst, src);
        }
    };

    // ---- A chunk gather into regs: 2048 float4, 4 per thread
    auto loadA = [&](float4* dst, int c) {
        const bool fromFull = (c < 4);
        const int  kb = (c & 3) * KC;
#pragma unroll
        for (int j = 0; j < 4; ++j) {
            int id = tid + j * THREADS;      // 0..2047
            int r  = id >> 4;                // 0..127
            int c4 = (id & 15) << 2;         // 0..60
            const float* src;
            if (fromFull) {
                src = h_full + (size_t)rowidx[r] * DIM;
            } else {
                int m = tileM + r;
                if (m >= Mrows) m = Mrows - 1;
                src = h_sub + (size_t)m * DIM;
            }
            dst[j] = __ldcs((const float4*)(src + kb + c4));
        }
    };

    // ---- A regs -> fp16 smem (stage st)
    auto storeA = [&](const float4* v, int st) {
        uint32_t abase = (uint32_t)(SM_A + st * A_STAGE);
#pragma unroll
        for (int j = 0; j < 4; ++j) {
            int id = tid + j * THREADS;
            int r  = id >> 4;
            int c4 = (id & 15) << 2;
            float4 q = v[j];
            __half2 p01 = __floats2half2_rn(q.x, q.y);
            __half2 p23 = __floats2half2_rn(q.z, q.w);
            *(uint2*)(smem + abase + r * ROWB + c4 * 2) =
                make_uint2(*(uint32_t*)&p01, *(uint32_t*)&p23);
        }
    };

    float acc[2][8][4];
#pragma unroll
    for (int mt = 0; mt < 2; ++mt)
#pragma unroll
        for (int nt = 0; nt < 8; ++nt)
#pragma unroll
            for (int q = 0; q < 4; ++q) acc[mt][nt][q] = 0.f;

    // ---- compute HALF a KC chunk (kk pair) from stage st
    auto computeH = [&](int st, int kh) {
        const uint32_t aB = sbase + SM_A + st * A_STAGE;
        const uint32_t bB = sbase + SM_B + st * B_STAGE;
#pragma unroll
        for (int kk = kh * 2; kk < kh * 2 + 2; ++kk) {
            uint32_t a[2][4];
#pragma unroll
            for (int mt = 0; mt < 2; ++mt) {
                uint32_t ra = (uint32_t)(warpM + mt * 16 + (lid & 15)) * ROWB
                            + (kk * 16 + (lid >> 4) * 8) * 2;
                ldsm4(a[mt], aB + ra);
            }
#pragma unroll
            for (int nt = 0; nt < 8; ++nt) {
                uint32_t rb = bB + (uint32_t)(warpN + nt * 8 + (lid >> 2)) * ROWB
                            + (kk * 16 + (lid & 3) * 2) * 2;
                uint32_t b0 = lds32(rb), b1v = lds32(rb + 16);
#pragma unroll
                for (int mt = 0; mt < 2; ++mt)
                    hmma(acc[mt][nt], a[mt], b0, b1v);
            }
        }
    };

    // ---- interleaved copy machinery: 1 row / thread-group-of-16 per group
    const float4* in4  = reinterpret_cast<const float4*>(h_full);
    float4*       out4 = reinterpret_cast<float4*>(out);
    const int cRowT = tid >> 4;          // 0..31
    const int cColT = tid & 15;          // f4 lane: cols cColT + i*16

    float4 cb[4];
    int  cRowG  = -1;
    bool cActive = false;

    auto copyLoad = [&](int c, int g) {
        int rl = c * rcChunk + g * halfR + cRowT;       // local row
        int rg = rows0 + rl;
        cActive = (cRowT < halfR) && (rl < rowsPer) && (rg < Nfull)
                  && (maskS[rl] == 0);
        cRowG = rg;
        if (cActive) {
            size_t base = ((size_t)rg << 6) + cColT;
#pragma unroll
            for (int i = 0; i < 4; ++i)
                cb[i] = __ldcs(&in4[base + i * 16]);
        }
    };
    auto copyStore = [&]() {
        if (cActive) {
            size_t base = ((size_t)cRowG << 6) + cColT;
#pragma unroll
            for (int i = 0; i < 4; ++i)
                __stcs(&out4[base + i * 16], cb[i]);
        }
    };

    // ---- prologue: chunk 0 into stage 0
    float4 aPre[4];
    issueB(0, 0);
    cp_commit();
    loadA(aPre, 0);
    storeA(aPre, 0);
    cp_wait0();
    __syncthreads();

    // ---- main loop: GEMM chunks with interleaved copy groups
#pragma unroll 1
    for (int c = 0; c < 8; ++c) {
        const int st = c & 1;
        if (c < 7) {
            issueB(c + 1, st ^ 1);
            cp_commit();
            loadA(aPre, c + 1);
        }
        copyLoad(c, 0);          // loads covered by computeH(...,0)
        computeH(st, 0);
        copyStore();
        copyLoad(c, 1);          // loads covered by computeH(...,1)
        computeH(st, 1);
        copyStore();
        if (c < 7) {
            storeA(aPre, st ^ 1);
            cp_wait0();
        }
        __syncthreads();
    }

    // ---- tail copy rows (if rowsPer > 8*rcChunk; none for default shape)
    for (int rl = 8 * rcChunk + cRowT; rl < rowsPer; rl += 32) {
        int rg = rows0 + rl;
        if (rg < Nfull) {
            bool cp = (rl < 1024) ? (maskS[rl] == 0) : (g_mask[rg] == 0);
            if (cp) {
                size_t base = ((size_t)rg << 6) + cColT;
#pragma unroll
                for (int i = 0; i < 4; ++i)
                    __stcs(&out4[base + i * 16], __ldcs(&in4[base + i * 16]));
            }
        }
    }

    // ---- epilogue: bias add + scatter (streaming stores)
    {
        const int r0 = lid >> 2;
        const int nc = (lid & 3) * 2;
#pragma unroll
        for (int mt = 0; mt < 2; ++mt) {
#pragma unroll
            for (int half = 0; half < 2; ++half) {
                int row = warpM + mt * 16 + r0 + half * 8;
                int mg  = tileM + row;
                if (mg < Mrows) {
                    float* orow = out + (size_t)rowidx[row] * DIM + warpN;
#pragma unroll
                    for (int nt = 0; nt < 8; ++nt) {
                        float2 bv = *(const float2*)&biasS[warpN + nt * 8 + nc];
                        float2 v;
                        v.x = acc[mt][nt][half * 2 + 0] + bv.x;
                        v.y = acc[mt][nt][half * 2 + 1] + bv.y;
                        __stcs((float2*)(orow + nt * 8 + nc), v);
                    }
                }
            }
        }
    }
}

// ---------------- launch ----------------
extern "C" void kernel_launch(void* const* d_in, const int* in_sizes, int n_in,
                              void* d_out, int out_size) {
    const float* h_full = (const float*)d_in[0];
    const float* h_sub  = (const float*)d_in[1];
    const float* W1     = (const float*)d_in[2];
    const float* b1     = (const float*)d_in[3];
    const float* W2     = (const float*)d_in[4];
    const float* b2     = (const float*)d_in[5];
    const void*  idx    = d_in[6];
    float*       out    = (float*)d_out;

    const int dim   = in_sizes[3];
    const int Mrows = in_sizes[1] / dim;
    const int Nfull = in_sizes[0] / dim;

    static cudaStream_t sPrep = nullptr;
    static cudaEvent_t  evDet = nullptr, evMask = nullptr;
    if (!sPrep) {
        cudaStreamCreateWithFlags(&sPrep, cudaStreamNonBlocking);
        cudaEventCreateWithFlags(&evDet, cudaEventDisableTiming);
        cudaEventCreateWithFlags(&evMask, cudaEventDisableTiming);
    }

    cudaFuncSetAttribute(merge_gemm_fp16,
                         cudaFuncAttributeMaxDynamicSharedMemorySize, SM_TOTAL);

    // ---- prep, parallel across streams ----
    const int maskWords = (Nfull + 15) / 16;
    clear_mask<<<(maskWords + 255) / 256, 256, 0, sPrep>>>(maskWords);

    detect_idx_kernel<<<1, 1>>>(idx, Mrows, (long long)Nfull);
    cudaEventRecord(evDet, 0);
    convert_W<<<(256 * 512 + 255) / 256, 256>>>(W1, W2);

    cudaStreamWaitEvent(sPrep, evDet, 0);
    set_mask<<<(Mrows + 255) / 256, 256, 0, sPrep>>>(idx, Mrows);
    cudaEventRecord(evMask, sPrep);
    cudaStreamWaitEvent(0, evMask, 0);

    // ---- fused GEMM + copy ----
    const int tiles   = (Mrows + BM - 1) / BM;
    const int rowsPer = (Nfull + tiles - 1) / tiles;
    merge_gemm_fp16<<<tiles, THREADS, SM_TOTAL>>>(h_full, h_sub, b1, b2, idx,
                                                  out, Mrows, Nfull, rowsPer);
}